// round 8
// baseline (speedup 1.0000x reference)
#include <cuda_runtime.h>
#include <cuda_fp16.h>
#include <cstdint>
#include <cstddef>

// Problem constants
#define BB 8
#define TT 2048
#define DD 1024

// GEMM tiling (fp16 operands, fp32 accum)
#define BM 128
#define BN 128
#define BK 64            // K halves per stage (128 B rows)
#define SROW 72          // smem row stride in halves (144B): conflict-free LDSM/STS
#define TILE_HALVES (BM * SROW)
#define SMEM_BYTES  (2 * 2 * TILE_HALVES * 2)   // 73728 B

// Scratch (device globals = allowed)
__device__ __half d_Wth[DD * DD];               // W^T as half [N][K]
__device__ __half d_x0h[BB * TT * DD];
__device__ __half d_x1h[BB * TT * DD];
__device__ __half d_attnh[BB * TT * DD];

__device__ __forceinline__ void cp_async16(uint32_t saddr, const void* g) {
    asm volatile("cp.async.cg.shared.global [%0], [%1], 16;" :: "r"(saddr), "l"(g));
}
__device__ __forceinline__ void cp_commit() { asm volatile("cp.async.commit_group;"); }
__device__ __forceinline__ void cp_wait0()  { asm volatile("cp.async.wait_group 0;"); }

__device__ __forceinline__ void mma_f16(float c[4], const uint32_t a[4], uint32_t b0, uint32_t b1) {
    asm volatile(
        "mma.sync.aligned.m16n8k16.row.col.f32.f16.f16.f32 "
        "{%0,%1,%2,%3}, {%4,%5,%6,%7}, {%8,%9}, {%0,%1,%2,%3};\n"
        : "+f"(c[0]), "+f"(c[1]), "+f"(c[2]), "+f"(c[3])
        : "r"(a[0]), "r"(a[1]), "r"(a[2]), "r"(a[3]), "r"(b0), "r"(b1));
}
__device__ __forceinline__ void ldsm_x4(uint32_t r[4], uint32_t saddr) {
    asm volatile("ldmatrix.sync.aligned.m8n8.x4.shared.b16 {%0,%1,%2,%3}, [%4];"
                 : "=r"(r[0]), "=r"(r[1]), "=r"(r[2]), "=r"(r[3]) : "r"(saddr));
}

// ---------------------------------------------------------------- pre-passes
__global__ __launch_bounds__(256) void conv_f2h(const float* __restrict__ src,
                                                __half* __restrict__ dst, int n) {
    int i = (blockIdx.x * 256 + threadIdx.x) * 4;
    if (i >= n) return;
    float4 v = *(const float4*)(src + i);
    __half2 h0 = __floats2half2_rn(v.x, v.y);
    __half2 h1 = __floats2half2_rn(v.z, v.w);
    *(uint32_t*)(dst + i)     = *(uint32_t*)&h0;
    *(uint32_t*)(dst + i + 2) = *(uint32_t*)&h1;
}

__global__ void transposeW_h(const float* __restrict__ W, __half* __restrict__ Wt) {
    __shared__ float tile[32][33];
    int bx = blockIdx.x * 32, by = blockIdx.y * 32;
    int tx = threadIdx.x, ty = threadIdx.y;
#pragma unroll
    for (int i = 0; i < 32; i += 8)
        tile[ty + i][tx] = W[(size_t)(by + ty + i) * DD + bx + tx];
    __syncthreads();
#pragma unroll
    for (int i = 0; i < 32; i += 8)
        Wt[(size_t)(bx + ty + i) * DD + by + tx] = __float2half_rn(tile[tx][ty + i]);
}

__global__ __launch_bounds__(256) void softmax_rows(float* __restrict__ data,
                                                    __half* __restrict__ data_h) {
    __shared__ float redmax[8];
    __shared__ float redsum[8];
    const size_t rowoff = (size_t)blockIdx.x * DD;
    float* p = data + rowoff;
    __half* ph = data_h + rowoff;
    const int tid = threadIdx.x;

    float4 v = *(float4*)(p + tid * 4);
    float m = fmaxf(fmaxf(v.x, v.y), fmaxf(v.z, v.w));
#pragma unroll
    for (int o = 16; o > 0; o >>= 1) m = fmaxf(m, __shfl_xor_sync(0xffffffffu, m, o));
    if ((tid & 31) == 0) redmax[tid >> 5] = m;
    __syncthreads();
    m = redmax[0];
#pragma unroll
    for (int i = 1; i < 8; i++) m = fmaxf(m, redmax[i]);

    v.x = __expf(v.x - m); v.y = __expf(v.y - m);
    v.z = __expf(v.z - m); v.w = __expf(v.w - m);
    float s = v.x + v.y + v.z + v.w;
#pragma unroll
    for (int o = 16; o > 0; o >>= 1) s += __shfl_xor_sync(0xffffffffu, s, o);
    if ((tid & 31) == 0) redsum[tid >> 5] = s;
    __syncthreads();
    s = redsum[0];
#pragma unroll
    for (int i = 1; i < 8; i++) s += redsum[i];

    float inv = 1.0f / s;
    v.x *= inv; v.y *= inv; v.z *= inv; v.w *= inv;
    *(float4*)(p + tid * 4) = v;
    __half2 h0 = __floats2half2_rn(v.x, v.y);
    __half2 h1 = __floats2half2_rn(v.z, v.w);
    *(uint32_t*)(ph + tid * 4)     = *(uint32_t*)&h0;
    *(uint32_t*)(ph + tid * 4 + 2) = *(uint32_t*)&h1;
}

// ---------------------------------------------------------------- fp16 tensor GEMM
// C[M,N] = A[M,K] @ B[N,K]^T, half in / fp32 out.
// 128 threads (4 warps), block 128x128, warp tile 64x64, ldmatrix fragments.
__global__ __launch_bounds__(128, 2) void gemm_f16(
    const __half* __restrict__ A, const __half* __restrict__ Bm, float* __restrict__ C,
    int K, int lda, int ldb, int ldc,
    size_t aStride, size_t bStride, size_t cStride)
{
    extern __shared__ __align__(16) __half smem[];
    __half* sA = smem;                      // 2 * TILE_HALVES
    __half* sB = smem + 2 * TILE_HALVES;

    A  += (size_t)blockIdx.z * aStride;
    Bm += (size_t)blockIdx.z * bStride;
    C  += (size_t)blockIdx.z * cStride;

    const int tid  = threadIdx.x;
    const int warp = tid >> 5;
    const int lane = tid & 31;
    const int wm = warp & 1;      // 2 warps along M -> 64 rows
    const int wn = warp >> 1;     // 2 warps along N -> 64 cols
    const int g = lane >> 2;      // 0..7
    const int t = lane & 3;       // 0..3

    // ldmatrix per-lane row/koffset: sets {m+0-7@k, m+8-15@k, m+0-7@k+8, m+8-15@k+8}
    const int lrow = (lane & 7) + ((lane >> 3) & 1) * 8;  // 0..15
    const int lkh  = (lane >> 4) * 8;                     // 0 or 8 halves

    // global->smem: 1024 16B chunks per operand, 8 per thread
    const int r0 = tid >> 3;          // rows r0 + i*16
    const int c0 = (tid & 7) * 8;     // halves

    const __half* Ag = A  + (size_t)((size_t)blockIdx.y * BM + r0) * lda + c0;
    const __half* Bg = Bm + (size_t)((size_t)blockIdx.x * BN + r0) * ldb + c0;

    const uint32_t smem_u = (uint32_t)__cvta_generic_to_shared(smem);
    const uint32_t sA_st = smem_u + (uint32_t)(r0 * SROW + c0) * 2u;
    const uint32_t sB_st = smem_u + (uint32_t)(2 * TILE_HALVES + r0 * SROW + c0) * 2u;

    // fragment-load bases (lane-dependent)
    const uint32_t aFragBase = smem_u + (uint32_t)(((wm * 64 + lrow) * SROW) + lkh) * 2u;
    const uint32_t bFragBase = smem_u + (uint32_t)((2 * TILE_HALVES) + ((wn * 64 + lrow) * SROW) + lkh) * 2u;

    float c[4][8][4];
#pragma unroll
    for (int mt = 0; mt < 4; mt++)
#pragma unroll
        for (int nt = 0; nt < 8; nt++)
#pragma unroll
            for (int i = 0; i < 4; i++) c[mt][nt][i] = 0.f;

    // prologue: stage 0 into buffer 0
#pragma unroll
    for (int i = 0; i < 8; i++) {
        cp_async16(sA_st + (uint32_t)(i * 16 * SROW) * 2u, Ag + (size_t)i * 16 * lda);
        cp_async16(sB_st + (uint32_t)(i * 16 * SROW) * 2u, Bg + (size_t)i * 16 * ldb);
    }
    cp_commit();
    cp_wait0();
    __syncthreads();

    int buf = 0;
    for (int k0 = 0; k0 < K; k0 += BK) {
        if (k0 + BK < K) {
            const int nb = buf ^ 1;
            const __half* Ap = Ag + (k0 + BK);
            const __half* Bp = Bg + (k0 + BK);
            const uint32_t da = sA_st + (uint32_t)(nb * TILE_HALVES) * 2u;
            const uint32_t db = sB_st + (uint32_t)(nb * TILE_HALVES) * 2u;
#pragma unroll
            for (int i = 0; i < 8; i++) {
                cp_async16(da + (uint32_t)(i * 16 * SROW) * 2u, Ap + (size_t)i * 16 * lda);
                cp_async16(db + (uint32_t)(i * 16 * SROW) * 2u, Bp + (size_t)i * 16 * ldb);
            }
            cp_commit();
        }

        const uint32_t aB = aFragBase + (uint32_t)(buf * TILE_HALVES) * 2u;
        const uint32_t bB = bFragBase + (uint32_t)(buf * TILE_HALVES) * 2u;

#pragma unroll
        for (int ks = 0; ks < 4; ks++) {
            const uint32_t kb = (uint32_t)(ks * 16 * 2);   // byte offset for k
            uint32_t a[4][4], b[4][4];
#pragma unroll
            for (int mt = 0; mt < 4; mt++)
                ldsm_x4(a[mt], aB + (uint32_t)(mt * 16 * SROW) * 2u + kb);
#pragma unroll
            for (int j = 0; j < 4; j++)
                ldsm_x4(b[j], bB + (uint32_t)(j * 16 * SROW) * 2u + kb);
            // b[j] = { b0(nt=2j), b0(nt=2j+1), b1(nt=2j), b1(nt=2j+1) }
#pragma unroll
            for (int mt = 0; mt < 4; mt++)
#pragma unroll
                for (int nt = 0; nt < 8; nt++)
                    mma_f16(c[mt][nt], a[mt], b[nt >> 1][nt & 1], b[nt >> 1][2 + (nt & 1)]);
        }

        cp_wait0();
        __syncthreads();
        buf ^= 1;
    }

    // epilogue
    const int mbase = blockIdx.y * BM + wm * 64;
    const int nbase = blockIdx.x * BN + wn * 64;
#pragma unroll
    for (int mt = 0; mt < 4; mt++) {
        int row0 = mbase + mt * 16 + g;
#pragma unroll
        for (int nt = 0; nt < 8; nt++) {
            int col = nbase + nt * 8 + t * 2;
            float2 v0 = make_float2(c[mt][nt][0], c[mt][nt][1]);
            *(float2*)&C[(size_t)row0 * ldc + col] = v0;
            float2 v1 = make_float2(c[mt][nt][2], c[mt][nt][3]);
            *(float2*)&C[(size_t)(row0 + 8) * ldc + col] = v1;
        }
    }
}

// ---------------------------------------------------------------- launch
extern "C" void kernel_launch(void* const* d_in, const int* in_sizes, int n_in,
                              void* d_out, int out_size) {
    const float* x0 = (const float*)d_in[0];   // [B,T,D]
    const float* x1 = (const float*)d_in[1];   // [B,T,D]
    const float* W  = (const float*)d_in[2];   // [D,D]
    float* out  = (float*)d_out;
    float* ws   = out;                                        // [B,T,T]
    float* attn = out + (size_t)BB * TT * TT;                 // [B,T,D]

    __half *wt_p, *x0h_p, *x1h_p, *attnh_p;
    cudaGetSymbolAddress((void**)&wt_p,   d_Wth);
    cudaGetSymbolAddress((void**)&x0h_p,  d_x0h);
    cudaGetSymbolAddress((void**)&x1h_p,  d_x1h);
    cudaGetSymbolAddress((void**)&attnh_p, d_attnh);

    static bool attr_done = false;
    if (!attr_done) {
        cudaFuncSetAttribute(gemm_f16, cudaFuncAttributeMaxDynamicSharedMemorySize, SMEM_BYTES);
        attr_done = true;
    }

    const int nElem = BB * TT * DD;

    // 0) convert inputs to fp16 once
    conv_f2h<<<nElem / 1024, 256>>>(x0, x0h_p, nElem);
    conv_f2h<<<nElem / 1024, 256>>>(x1, x1h_p, nElem);
    transposeW_h<<<dim3(DD / 32, DD / 32), dim3(32, 8)>>>(W, wt_p);

    // 1) logits = x1 @ W -> fp32 into attention region of d_out
    gemm_f16<<<dim3(DD / BN, (BB * TT) / BM, 1), 128, SMEM_BYTES>>>(
        x1h_p, wt_p, attn, DD, DD, DD, DD, 0, 0, 0);

    // 2) softmax in place (fp32) + fp16 copy
    softmax_rows<<<BB * TT, 256>>>(attn, attnh_p);

    // 3) weighted_sum[b] = attn[b] @ x0[b]^T
    gemm_f16<<<dim3(TT / BN, TT / BM, BB), 128, SMEM_BYTES>>>(
        attnh_p, x0h_p, ws, DD, DD, DD, TT,
        (size_t)TT * DD, (size_t)TT * DD, (size_t)TT * TT);
}